// round 1
// baseline (speedup 1.0000x reference)
#include <cuda_runtime.h>

// Problem constants (B=64, N=2048 -> T tokens)
#define T_TOKENS 131072
#define DIM 256        // model dim D
#define HID 512        // hidden H
#define NE 8           // experts
// top-k = 2

// ---------------------------------------------------------------------------
// Device scratch (static: no allocations allowed)
// ---------------------------------------------------------------------------
__device__ int   g_cnt[NE];                 // tokens routed to expert e (also "load" count)
__device__ float g_imp[NE];                 // sum over tokens of softmax prob for e
__device__ int   g_tok[NE][T_TOKENS];       // dispatched token ids
__device__ float g_wt [NE][T_TOKENS];       // combine weights

__global__ void k_zero() {
    int i = threadIdx.x;
    if (i < NE) { g_cnt[i] = 0; g_imp[i] = 0.0f; }
}

// ---------------------------------------------------------------------------
// Router: logits -> softmax -> top-2 -> renormalized combine weights,
// per-expert dispatch lists, importance accumulation for aux loss.
// One thread per token.
// ---------------------------------------------------------------------------
__global__ __launch_bounds__(256) void k_router(const float* __restrict__ x,
                                                const float* __restrict__ rw,
                                                const float* __restrict__ rb) {
    __shared__ __align__(16) float s_w[NE * DIM];   // transposed: [e][d]
    __shared__ float s_b[NE];
    __shared__ float s_imp[NE];

    int tid = threadIdx.x;
    for (int i = tid; i < NE * DIM; i += 256) {
        int e = i >> 8, d = i & 255;
        s_w[i] = rw[d * NE + e];                    // router_w is [D][E]
    }
    if (tid < NE) { s_b[tid] = rb[tid]; s_imp[tid] = 0.0f; }
    __syncthreads();

    int t = blockIdx.x * 256 + tid;
    const float4* xr = reinterpret_cast<const float4*>(x + (size_t)t * DIM);

    float lg[NE];
#pragma unroll
    for (int e = 0; e < NE; e++) lg[e] = s_b[e];

    for (int i = 0; i < DIM / 4; i++) {
        float4 v = xr[i];
#pragma unroll
        for (int e = 0; e < NE; e++) {
            float4 w = *reinterpret_cast<const float4*>(&s_w[e * DIM + i * 4]);
            lg[e] += v.x * w.x + v.y * w.y + v.z * w.z + v.w * w.w;
        }
    }

    // softmax over 8
    float m = lg[0];
#pragma unroll
    for (int e = 1; e < NE; e++) m = fmaxf(m, lg[e]);
    float p[NE]; float s = 0.0f;
#pragma unroll
    for (int e = 0; e < NE; e++) { p[e] = expf(lg[e] - m); s += p[e]; }
    float inv = 1.0f / s;
#pragma unroll
    for (int e = 0; e < NE; e++) p[e] *= inv;

    // top-2 (ties -> lowest index, matching jax.lax.top_k)
    float v1 = -1.0f; int i1 = 0;
#pragma unroll
    for (int e = 0; e < NE; e++) { if (p[e] > v1) { v1 = p[e]; i1 = e; } }
    float v2 = -1.0f; int i2 = (i1 == 0) ? 1 : 0;
#pragma unroll
    for (int e = 0; e < NE; e++) { if (e != i1 && p[e] > v2) { v2 = p[e]; i2 = e; } }

    float denom = v1 + v2 + 1e-9f;
    float c1 = v1 / denom, c2 = v2 / denom;

    int s1 = atomicAdd(&g_cnt[i1], 1);
    g_tok[i1][s1] = t; g_wt[i1][s1] = c1;
    int s2 = atomicAdd(&g_cnt[i2], 1);
    g_tok[i2][s2] = t; g_wt[i2][s2] = c2;

#pragma unroll
    for (int e = 0; e < NE; e++) atomicAdd(&s_imp[e], p[e]);
    __syncthreads();
    if (tid < NE) atomicAdd(&g_imp[tid], s_imp[tid]);
}

// ---------------------------------------------------------------------------
// Shared expert: out[t] = relu(x[t] @ sw1 + sb1) @ sw2 + sb2 (direct write)
// 64-token tile per block, h never leaves SMEM.
// Thread (tx = tid&15, ty = tid>>4):
//   GEMM1 tile: rows ty*4..+4, h cols tx*4..+4       (conflict-free)
//   GEMM2 tile: rows ty*4..+4, n cols {j*64 + tx*4}  (conflict-free)
// ---------------------------------------------------------------------------
__global__ __launch_bounds__(256, 2) void k_shared(
    const float* __restrict__ x,  const float* __restrict__ w1,
    const float* __restrict__ b1, const float* __restrict__ w2,
    const float* __restrict__ b2, float* __restrict__ out)
{
    __shared__ __align__(16) float sA[64 * 64];
    __shared__ __align__(16) float sH[64 * 64];
    __shared__ __align__(16) float sW[64 * 64];

    int tid = threadIdx.x;
    int tx = tid & 15, ty = tid >> 4;
    int ty4 = ty * 4;
    int m0 = blockIdx.x * 64;

    float acc[4][16];
#pragma unroll
    for (int i = 0; i < 4; i++)
#pragma unroll
        for (int j = 0; j < 16; j++) acc[i][j] = 0.0f;

#pragma unroll 1
    for (int hc = 0; hc < HID; hc += 64) {
        float hacc[4][4] = {};

#pragma unroll 1
        for (int kc = 0; kc < DIM; kc += 64) {
            __syncthreads();
#pragma unroll
            for (int u = 0; u < 4; u++) {
                int i = tid + u * 256;
                int r = i >> 4, c = i & 15;
                *reinterpret_cast<float4*>(&sA[r * 64 + c * 4]) =
                    *reinterpret_cast<const float4*>(&x[(size_t)(m0 + r) * DIM + kc + c * 4]);
                *reinterpret_cast<float4*>(&sW[r * 64 + c * 4]) =
                    *reinterpret_cast<const float4*>(&w1[(size_t)(kc + r) * HID + hc + c * 4]);
            }
            __syncthreads();
#pragma unroll
            for (int k = 0; k < 64; k += 4) {
                float4 av[4];
#pragma unroll
                for (int i = 0; i < 4; i++)
                    av[i] = *reinterpret_cast<const float4*>(&sA[(ty4 + i) * 64 + k]);
#pragma unroll
                for (int kk = 0; kk < 4; kk++) {
                    float4 wv = *reinterpret_cast<const float4*>(&sW[(k + kk) * 64 + tx * 4]);
#pragma unroll
                    for (int i = 0; i < 4; i++) {
                        float a = reinterpret_cast<const float*>(&av[i])[kk];
                        hacc[i][0] += a * wv.x; hacc[i][1] += a * wv.y;
                        hacc[i][2] += a * wv.z; hacc[i][3] += a * wv.w;
                    }
                }
            }
        }
        __syncthreads();
        {
            float4 bv = *reinterpret_cast<const float4*>(&b1[hc + tx * 4]);
#pragma unroll
            for (int i = 0; i < 4; i++) {
                float4 hv;
                hv.x = fmaxf(hacc[i][0] + bv.x, 0.0f);
                hv.y = fmaxf(hacc[i][1] + bv.y, 0.0f);
                hv.z = fmaxf(hacc[i][2] + bv.z, 0.0f);
                hv.w = fmaxf(hacc[i][3] + bv.w, 0.0f);
                *reinterpret_cast<float4*>(&sH[(ty4 + i) * 64 + tx * 4]) = hv;
            }
        }
        __syncthreads();

#pragma unroll 1
        for (int s2 = 0; s2 < 4; s2++) {
            __syncthreads();
#pragma unroll
            for (int u = 0; u < 4; u++) {
                int i = tid + u * 256;
                int r = i >> 6, c = i & 63;
                *reinterpret_cast<float4*>(&sW[r * 256 + c * 4]) =
                    *reinterpret_cast<const float4*>(&w2[(size_t)(hc + s2 * 16 + r) * DIM + c * 4]);
            }
            __syncthreads();
#pragma unroll
            for (int k = 0; k < 16; k += 4) {
                float4 av[4];
#pragma unroll
                for (int i = 0; i < 4; i++)
                    av[i] = *reinterpret_cast<const float4*>(&sH[(ty4 + i) * 64 + s2 * 16 + k]);
#pragma unroll
                for (int kk = 0; kk < 4; kk++) {
                    float4 wv[4];
#pragma unroll
                    for (int j = 0; j < 4; j++)
                        wv[j] = *reinterpret_cast<const float4*>(&sW[(k + kk) * 256 + j * 64 + tx * 4]);
#pragma unroll
                    for (int i = 0; i < 4; i++) {
                        float a = reinterpret_cast<const float*>(&av[i])[kk];
#pragma unroll
                        for (int j = 0; j < 4; j++) {
                            acc[i][j * 4 + 0] += a * wv[j].x;
                            acc[i][j * 4 + 1] += a * wv[j].y;
                            acc[i][j * 4 + 2] += a * wv[j].z;
                            acc[i][j * 4 + 3] += a * wv[j].w;
                        }
                    }
                }
            }
        }
    }

    float4 b2v[4];
#pragma unroll
    for (int j = 0; j < 4; j++)
        b2v[j] = *reinterpret_cast<const float4*>(&b2[j * 64 + tx * 4]);
#pragma unroll
    for (int i = 0; i < 4; i++) {
        size_t row = (size_t)(m0 + ty4 + i) * DIM;
#pragma unroll
        for (int j = 0; j < 4; j++) {
            float4 o;
            o.x = acc[i][j * 4 + 0] + b2v[j].x;
            o.y = acc[i][j * 4 + 1] + b2v[j].y;
            o.z = acc[i][j * 4 + 2] + b2v[j].z;
            o.w = acc[i][j * 4 + 3] + b2v[j].w;
            *reinterpret_cast<float4*>(&out[row + j * 64 + tx * 4]) = o;
        }
    }
}

// ---------------------------------------------------------------------------
// Routed experts: same fused GEMM over gathered token lists.
// grid = (2048 tiles, 8 experts); blocks beyond count[e] exit.
// Epilogue: out[tok] += cw * (y + b2)  via atomicAdd (shared kernel ran first).
// ---------------------------------------------------------------------------
__global__ __launch_bounds__(256, 2) void k_routed(
    const float* __restrict__ x,      const float* __restrict__ w1_all,
    const float* __restrict__ b1_all, const float* __restrict__ w2_all,
    const float* __restrict__ b2_all, float* __restrict__ out)
{
    int e = blockIdx.y;
    int cnt = g_cnt[e];
    int m0 = blockIdx.x * 64;
    if (m0 >= cnt) return;

    const float* w1 = w1_all + (size_t)e * DIM * HID;
    const float* b1 = b1_all + (size_t)e * HID;
    const float* w2 = w2_all + (size_t)e * HID * DIM;
    const float* b2 = b2_all + (size_t)e * DIM;

    __shared__ __align__(16) float sA[64 * 64];
    __shared__ __align__(16) float sH[64 * 64];
    __shared__ __align__(16) float sW[64 * 64];

    int tid = threadIdx.x;
    int tx = tid & 15, ty = tid >> 4;
    int ty4 = ty * 4;

    float acc[4][16];
#pragma unroll
    for (int i = 0; i < 4; i++)
#pragma unroll
        for (int j = 0; j < 16; j++) acc[i][j] = 0.0f;

#pragma unroll 1
    for (int hc = 0; hc < HID; hc += 64) {
        float hacc[4][4] = {};

#pragma unroll 1
        for (int kc = 0; kc < DIM; kc += 64) {
            __syncthreads();
#pragma unroll
            for (int u = 0; u < 4; u++) {
                int i = tid + u * 256;
                int r = i >> 4, c = i & 15;
                int idx = m0 + r;
                int tok = (idx < cnt) ? g_tok[e][idx] : 0;
                *reinterpret_cast<float4*>(&sA[r * 64 + c * 4]) =
                    *reinterpret_cast<const float4*>(&x[(size_t)tok * DIM + kc + c * 4]);
                *reinterpret_cast<float4*>(&sW[r * 64 + c * 4]) =
                    *reinterpret_cast<const float4*>(&w1[(size_t)(kc + r) * HID + hc + c * 4]);
            }
            __syncthreads();
#pragma unroll
            for (int k = 0; k < 64; k += 4) {
                float4 av[4];
#pragma unroll
                for (int i = 0; i < 4; i++)
                    av[i] = *reinterpret_cast<const float4*>(&sA[(ty4 + i) * 64 + k]);
#pragma unroll
                for (int kk = 0; kk < 4; kk++) {
                    float4 wv = *reinterpret_cast<const float4*>(&sW[(k + kk) * 64 + tx * 4]);
#pragma unroll
                    for (int i = 0; i < 4; i++) {
                        float a = reinterpret_cast<const float*>(&av[i])[kk];
                        hacc[i][0] += a * wv.x; hacc[i][1] += a * wv.y;
                        hacc[i][2] += a * wv.z; hacc[i][3] += a * wv.w;
                    }
                }
            }
        }
        __syncthreads();
        {
            float4 bv = *reinterpret_cast<const float4*>(&b1[hc + tx * 4]);
#pragma unroll
            for (int i = 0; i < 4; i++) {
                float4 hv;
                hv.x = fmaxf(hacc[i][0] + bv.x, 0.0f);
                hv.y = fmaxf(hacc[i][1] + bv.y, 0.0f);
                hv.z = fmaxf(hacc[i][2] + bv.z, 0.0f);
                hv.w = fmaxf(hacc[i][3] + bv.w, 0.0f);
                *reinterpret_cast<float4*>(&sH[(ty4 + i) * 64 + tx * 4]) = hv;
            }
        }
        __syncthreads();

#pragma unroll 1
        for (int s2 = 0; s2 < 4; s2++) {
            __syncthreads();
#pragma unroll
            for (int u = 0; u < 4; u++) {
                int i = tid + u * 256;
                int r = i >> 6, c = i & 63;
                *reinterpret_cast<float4*>(&sW[r * 256 + c * 4]) =
                    *reinterpret_cast<const float4*>(&w2[(size_t)(hc + s2 * 16 + r) * DIM + c * 4]);
            }
            __syncthreads();
#pragma unroll
            for (int k = 0; k < 16; k += 4) {
                float4 av[4];
#pragma unroll
                for (int i = 0; i < 4; i++)
                    av[i] = *reinterpret_cast<const float4*>(&sH[(ty4 + i) * 64 + s2 * 16 + k]);
#pragma unroll
                for (int kk = 0; kk < 4; kk++) {
                    float4 wv[4];
#pragma unroll
                    for (int j = 0; j < 4; j++)
                        wv[j] = *reinterpret_cast<const float4*>(&sW[(k + kk) * 256 + j * 64 + tx * 4]);
#pragma unroll
                    for (int i = 0; i < 4; i++) {
                        float a = reinterpret_cast<const float*>(&av[i])[kk];
#pragma unroll
                        for (int j = 0; j < 4; j++) {
                            acc[i][j * 4 + 0] += a * wv[j].x;
                            acc[i][j * 4 + 1] += a * wv[j].y;
                            acc[i][j * 4 + 2] += a * wv[j].z;
                            acc[i][j * 4 + 3] += a * wv[j].w;
                        }
                    }
                }
            }
        }
    }

    float4 b2v[4];
#pragma unroll
    for (int j = 0; j < 4; j++)
        b2v[j] = *reinterpret_cast<const float4*>(&b2[j * 64 + tx * 4]);

#pragma unroll
    for (int i = 0; i < 4; i++) {
        int idx = m0 + ty4 + i;
        if (idx >= cnt) continue;
        int tok = g_tok[e][idx];
        float cw = g_wt[e][idx];
        size_t row = (size_t)tok * DIM;
#pragma unroll
        for (int j = 0; j < 4; j++) {
            float bx[4] = { b2v[j].x, b2v[j].y, b2v[j].z, b2v[j].w };
#pragma unroll
            for (int c = 0; c < 4; c++) {
                atomicAdd(&out[row + j * 64 + tx * 4 + c],
                          cw * (acc[i][j * 4 + c] + bx[c]));
            }
        }
    }
}

// ---------------------------------------------------------------------------
// Aux loss: aux = E * sum_e importance[e] * load[e]
// ---------------------------------------------------------------------------
__global__ void k_aux(float* out_aux) {
    if (threadIdx.x == 0) {
        float a = 0.0f;
        for (int e = 0; e < NE; e++) {
            float imp  = g_imp[e] / (float)T_TOKENS;
            float load = (float)g_cnt[e] / (float)(2 * T_TOKENS);
            a += imp * load;
        }
        out_aux[0] = (float)NE * a;
    }
}

// ---------------------------------------------------------------------------
extern "C" void kernel_launch(void* const* d_in, const int* in_sizes, int n_in,
                              void* d_out, int out_size) {
    const float* x   = (const float*)d_in[0];
    const float* rw  = (const float*)d_in[1];
    const float* rb  = (const float*)d_in[2];
    const float* w1  = (const float*)d_in[3];
    const float* b1  = (const float*)d_in[4];
    const float* w2  = (const float*)d_in[5];
    const float* b2  = (const float*)d_in[6];
    const float* sw1 = (const float*)d_in[7];
    const float* sb1 = (const float*)d_in[8];
    const float* sw2 = (const float*)d_in[9];
    const float* sb2 = (const float*)d_in[10];
    float* out = (float*)d_out;

    (void)in_sizes; (void)n_in;

    k_zero<<<1, 32>>>();
    k_router<<<T_TOKENS / 256, 256>>>(x, rw, rb);
    k_shared<<<T_TOKENS / 64, 256>>>(x, sw1, sb1, sw2, sb2, out);
    dim3 grid_r(T_TOKENS / 64, NE);
    k_routed<<<grid_r, 256>>>(x, w1, b1, w2, b2, out);
    if (out_size > T_TOKENS * DIM) {
        k_aux<<<1, 32>>>(out + (size_t)T_TOKENS * DIM);
    }
}

// round 7
// speedup vs baseline: 2.2008x; 2.2008x over previous
#include <cuda_runtime.h>
#include <cuda_bf16.h>
#include <cstdint>

#define T_TOKENS 131072
#define DIM 256
#define HID 512
#define NE 8
#define NEXP 9

// ---------------- device scratch (~18 MB total) ----------------
__device__ int   g_cnt[NE];
__device__ float g_imp[NE];
__device__ int   g_tok[NE][T_TOKENS];
__device__ float g_wt [NE][T_TOKENS];

// Weight units: 32 units x 32KB per expert, bytes already in SMEM layout (swizzled)
__device__ __align__(16) __nv_bfloat16 gWU[NEXP][32 * 16384];
__device__ float gB1[NEXP][HID];
__device__ float gB2[NEXP][DIM];

// ---------------- PTX helpers (sm_80-era only; safe on sm_100) ----------------
__device__ __forceinline__ uint32_t smem_u32(const void* p) {
    uint32_t a;
    asm("{ .reg .u64 t; cvta.to.shared.u64 t, %1; cvt.u32.u64 %0, t; }" : "=r"(a) : "l"(p));
    return a;
}
__device__ __forceinline__ void cp16(uint32_t dst, const void* src) {
    asm volatile("cp.async.cg.shared.global [%0], [%1], 16;" :: "r"(dst), "l"(src));
}
#define CP_COMMIT() asm volatile("cp.async.commit_group;")
#define CP_WAIT1()  asm volatile("cp.async.wait_group 1;")

__device__ __forceinline__ void ldm4(uint32_t* r, uint32_t addr) {
    asm volatile("ldmatrix.sync.aligned.m8n8.x4.shared.b16 {%0,%1,%2,%3}, [%4];"
                 : "=r"(r[0]), "=r"(r[1]), "=r"(r[2]), "=r"(r[3]) : "r"(addr));
}
__device__ __forceinline__ void mma16816(float* c, const uint32_t* a, uint32_t b0, uint32_t b1) {
    asm volatile(
        "mma.sync.aligned.m16n8k16.row.col.f32.bf16.bf16.f32 "
        "{%0,%1,%2,%3}, {%4,%5,%6,%7}, {%8,%9}, {%0,%1,%2,%3};"
        : "+f"(c[0]), "+f"(c[1]), "+f"(c[2]), "+f"(c[3])
        : "r"(a[0]), "r"(a[1]), "r"(a[2]), "r"(a[3]), "r"(b0), "r"(b1));
}

__device__ __forceinline__ uint32_t pack_bf(__nv_bfloat16 a, __nv_bfloat16 b) {
    return (uint32_t)__bfloat16_as_ushort(a) | ((uint32_t)__bfloat16_as_ushort(b) << 16);
}

// ---------------- small kernels ----------------
__global__ void k_zero() {
    int i = threadIdx.x;
    if (i < NE) { g_cnt[i] = 0; g_imp[i] = 0.0f; }
}

__global__ __launch_bounds__(256) void k_router(const float* __restrict__ x,
                                                const float* __restrict__ rw,
                                                const float* __restrict__ rb) {
    __shared__ __align__(16) float s_w[NE * DIM];
    __shared__ float s_b[NE];
    __shared__ float s_imp[NE];
    int tid = threadIdx.x;
    for (int i = tid; i < NE * DIM; i += 256) {
        int e = i >> 8, d = i & 255;
        s_w[i] = rw[d * NE + e];
    }
    if (tid < NE) { s_b[tid] = rb[tid]; s_imp[tid] = 0.0f; }
    __syncthreads();

    int t = blockIdx.x * 256 + tid;
    const float4* xr = reinterpret_cast<const float4*>(x + (size_t)t * DIM);
    float lg[NE];
#pragma unroll
    for (int e = 0; e < NE; e++) lg[e] = s_b[e];
    for (int i = 0; i < DIM / 4; i++) {
        float4 v = xr[i];
#pragma unroll
        for (int e = 0; e < NE; e++) {
            float4 w = *reinterpret_cast<const float4*>(&s_w[e * DIM + i * 4]);
            lg[e] += v.x * w.x + v.y * w.y + v.z * w.z + v.w * w.w;
        }
    }
    float m = lg[0];
#pragma unroll
    for (int e = 1; e < NE; e++) m = fmaxf(m, lg[e]);
    float p[NE]; float s = 0.0f;
#pragma unroll
    for (int e = 0; e < NE; e++) { p[e] = expf(lg[e] - m); s += p[e]; }
    float inv = 1.0f / s;
#pragma unroll
    for (int e = 0; e < NE; e++) p[e] *= inv;

    float v1 = -1.0f; int i1 = 0;
#pragma unroll
    for (int e = 0; e < NE; e++) { if (p[e] > v1) { v1 = p[e]; i1 = e; } }
    float v2 = -1.0f; int i2 = (i1 == 0) ? 1 : 0;
#pragma unroll
    for (int e = 0; e < NE; e++) { if (e != i1 && p[e] > v2) { v2 = p[e]; i2 = e; } }

    float denom = v1 + v2 + 1e-9f;
    float c1 = v1 / denom, c2 = v2 / denom;

    int s1 = atomicAdd(&g_cnt[i1], 1);
    g_tok[i1][s1] = t; g_wt[i1][s1] = c1;
    int s2 = atomicAdd(&g_cnt[i2], 1);
    g_tok[i2][s2] = t; g_wt[i2][s2] = c2;

#pragma unroll
    for (int e = 0; e < NE; e++) atomicAdd(&s_imp[e], p[e]);
    __syncthreads();
    if (tid < NE) atomicAdd(&g_imp[tid], s_imp[tid]);
}

// W1T[h][d] -> units hc*8 + split*2 + ku ; slab [128 h-rows x 64 d] rows 128B swizzled
__global__ __launch_bounds__(256) void k_prepw1(const float* __restrict__ w1,
                                                const float* __restrict__ sw1) {
    int i = blockIdx.x * 256 + threadIdx.x;
    int e = i >> 17; int rem = i & 131071;
    int h = rem >> 8, d = rem & 255;
    float val = (e < 8) ? w1[((size_t)e * DIM + d) * HID + h] : sw1[(size_t)d * HID + h];
    __nv_bfloat16 hi = __float2bfloat16_rn(val);
    __nv_bfloat16 lo = __float2bfloat16_rn(val - __bfloat162float(hi));
    int hc = h >> 7, r = h & 127;
    int ku = d >> 7, ks = (d >> 6) & 1, kk = d & 63;
    uint32_t off = (uint32_t)(ks * 16384 + r * 128 + ((((kk >> 3) ^ (r & 7)) & 7) * 16) + (kk & 7) * 2);
    char* base = reinterpret_cast<char*>(&gWU[e][0]);
    *reinterpret_cast<__nv_bfloat16*>(base + (hc * 8 + 0 * 2 + ku) * 32768 + off) = hi;
    *reinterpret_cast<__nv_bfloat16*>(base + (hc * 8 + 1 * 2 + ku) * 32768 + off) = lo;
}

// W2T[d][h] -> units hc*8 + 4 + split*2 + ks2 ; slab per nh: [128 d-rows x 64 h]
__global__ __launch_bounds__(256) void k_prepw2(const float* __restrict__ w2,
                                                const float* __restrict__ sw2) {
    int i = blockIdx.x * 256 + threadIdx.x;
    int e = i >> 17; int rem = i & 131071;
    int h = rem >> 8, d = rem & 255;
    float val = (e < 8) ? w2[((size_t)e * HID + h) * DIM + d] : sw2[(size_t)h * DIM + d];
    __nv_bfloat16 hi = __float2bfloat16_rn(val);
    __nv_bfloat16 lo = __float2bfloat16_rn(val - __bfloat162float(hi));
    int hc = h >> 7, hin = h & 127, ks2 = hin >> 6, kk = hin & 63;
    int nh = d >> 7, r = d & 127;
    uint32_t off = (uint32_t)(nh * 16384 + r * 128 + ((((kk >> 3) ^ (r & 7)) & 7) * 16) + (kk & 7) * 2);
    char* base = reinterpret_cast<char*>(&gWU[e][0]);
    *reinterpret_cast<__nv_bfloat16*>(base + (hc * 8 + 4 + 0 * 2 + ks2) * 32768 + off) = hi;
    *reinterpret_cast<__nv_bfloat16*>(base + (hc * 8 + 4 + 1 * 2 + ks2) * 32768 + off) = lo;
}

__global__ __launch_bounds__(256) void k_prepb(const float* __restrict__ b1, const float* __restrict__ sb1,
                                               const float* __restrict__ b2, const float* __restrict__ sb2) {
    int i = blockIdx.x * 256 + threadIdx.x;
    if (i < NEXP * HID) {
        int e = i / HID, h = i % HID;
        gB1[e][h] = (e < 8) ? b1[e * HID + h] : sb1[h];
    } else if (i < NEXP * HID + NEXP * DIM) {
        int j = i - NEXP * HID;
        int e = j / DIM, d = j % DIM;
        gB2[e][d] = (e < 8) ? b2[e * DIM + d] : sb2[d];
    }
}

// ---------------- fused MoE tile kernel ----------------
// mode 0: shared expert (e=8), direct store to out
// mode 1: routed experts (e=blockIdx.y), atomicAdd(out, cw*(y+b2))
#define SM_A   0            // 64x512B (A hi)
#define SM_AL  32768        // A lo
#define SM_HH  65536        // 64x256B (H hi)
#define SM_HL  81920        // H lo
#define SM_W   98304        // 3 x 32KB ring
#define SM_B1  196608       // 512 floats
#define SM_B2  198656       // 256 floats
#define SMEM_TOTAL 199680

__global__ __launch_bounds__(256, 1) void k_moe(int mode, const float* __restrict__ x,
                                                float* __restrict__ out) {
    extern __shared__ __align__(1024) char smem[];
    bool sh = (mode == 0);
    int e = sh ? 8 : blockIdx.y;
    int cnt = sh ? T_TOKENS : g_cnt[e];
    int m0 = blockIdx.x * 64;
    if (m0 >= cnt) return;

    int tid = threadIdx.x, lane = tid & 31, wid = tid >> 5;
    int wm = wid >> 1, wn = wid & 1;
    uint32_t sb = smem_u32(smem);

    // ---- weight ring: prefetch first two units ----
    const char* WU = reinterpret_cast<const char*>(&gWU[e][0]);
#pragma unroll
    for (int p = 0; p < 2; p++) {
        uint32_t dst = sb + SM_W + p * 32768;
        const char* src = WU + p * 32768;
        for (int j = tid; j < 2048; j += 256) cp16(dst + j * 16, src + j * 16);
        CP_COMMIT();
    }

    // ---- A tile: gather fp32 x rows, split to bf16 hi/lo, store swizzled ----
    {
        int r = tid >> 2, cg = tid & 3;
        int idx = m0 + r;
        int tok = sh ? idx : ((idx < cnt) ? g_tok[e][idx] : g_tok[e][0]);
        const float4* src = reinterpret_cast<const float4*>(x + (size_t)tok * DIM);
        uint32_t rbase = (uint32_t)r << 9;
        int r7 = r & 7;
#pragma unroll
        for (int j = 0; j < 8; j++) {
            int c = cg * 8 + j;                      // 8-col chunk index (0..31)
            float4 v0 = src[c * 2];
            float4 v1 = src[c * 2 + 1];
            float f[8] = { v0.x, v0.y, v0.z, v0.w, v1.x, v1.y, v1.z, v1.w };
            uint32_t ph[4], pl[4];
#pragma unroll
            for (int q = 0; q < 4; q++) {
                __nv_bfloat16 h0 = __float2bfloat16_rn(f[2 * q]);
                __nv_bfloat16 h1 = __float2bfloat16_rn(f[2 * q + 1]);
                __nv_bfloat16 l0 = __float2bfloat16_rn(f[2 * q]     - __bfloat162float(h0));
                __nv_bfloat16 l1 = __float2bfloat16_rn(f[2 * q + 1] - __bfloat162float(h1));
                ph[q] = pack_bf(h0, h1);
                pl[q] = pack_bf(l0, l1);
            }
            uint32_t swo = (uint32_t)(((c & 24) | ((c ^ r7) & 7)) * 16);
            *reinterpret_cast<uint4*>(smem + SM_A + rbase + swo)  = make_uint4(ph[0], ph[1], ph[2], ph[3]);
            *reinterpret_cast<uint4*>(smem + SM_AL + rbase + swo) = make_uint4(pl[0], pl[1], pl[2], pl[3]);
        }
    }
    // biases
    for (int i = tid; i < HID; i += 256) reinterpret_cast<float*>(smem + SM_B1)[i] = gB1[e][i];
    if (tid < DIM) reinterpret_cast<float*>(smem + SM_B2)[tid] = gB2[e][tid];

    float acc2[16][4];
#pragma unroll
    for (int g = 0; g < 16; g++)
#pragma unroll
        for (int j = 0; j < 4; j++) acc2[g][j] = 0.0f;
    float acc1[8][4];

    // per-thread ldmatrix constants
    int rowA = (wm << 4) + (lane & 15);        // 0..63 (A/H rows)
    uint32_t aRowOff = (uint32_t)rowA << 9;    // *512
    uint32_t hRowOff = (uint32_t)rowA << 8;    // *256
    int ar7 = rowA & 7;
    int ka = (lane >> 4) & 1;                  // col-half select
    int rowB7 = (lane & 7) + ((lane & 16) ? 8 : 0);
    int bk = (lane >> 3) & 1;
    int l7 = lane & 7;
    int rE = (wm << 4) + (lane >> 2);
    int rE7 = rE & 7;

#pragma unroll 1
    for (int i = 0; i < 32; i++) {
        CP_WAIT1();
        __syncthreads();
        if (i + 2 < 32) {
            uint32_t dst = sb + SM_W + ((i + 2) % 3) * 32768;
            const char* src = WU + (i + 2) * 32768;
            for (int j = tid; j < 2048; j += 256) cp16(dst + j * 16, src + j * 16);
        }
        CP_COMMIT();

        int hc = i >> 3, u = i & 7;
        uint32_t wbase = sb + SM_W + (i % 3) * 32768;

        if (u < 4) {
            if (u == 0) {
#pragma unroll
                for (int g = 0; g < 8; g++)
#pragma unroll
                    for (int j = 0; j < 4; j++) acc1[g][j] = 0.0f;
            }
            int ku = u & 1;
            int np = (u < 2) ? 2 : 1;   // hi-W: A hi+lo ; lo-W: A hi
            int nb = wn << 6;
#pragma unroll
            for (int s = 0; s < 8; s++) {
                int ks = s >> 2;
                uint32_t ca = (uint32_t)(ku * 16 + s * 2 + ka);
                uint32_t swa = ((ca & 24) | ((ca ^ (uint32_t)ar7) & 7)) << 4;
                uint32_t ah[4], al[4];
                ldm4(ah, sb + SM_A + aRowOff + swa);
                if (np == 2) ldm4(al, sb + SM_AL + aRowOff + swa);
                uint32_t swb = (uint32_t)(((((s & 3) * 2 + bk) ^ l7) & 7) << 4);
                uint32_t bbase = wbase + (uint32_t)(ks * 16384) + swb;
#pragma unroll
                for (int gp = 0; gp < 4; gp++) {
                    uint32_t b[4];
                    ldm4(b, bbase + ((uint32_t)(nb + gp * 16 + rowB7) << 7));
                    mma16816(acc1[2 * gp],     ah, b[0], b[1]);
                    mma16816(acc1[2 * gp + 1], ah, b[2], b[3]);
                    if (np == 2) {
                        mma16816(acc1[2 * gp],     al, b[0], b[1]);
                        mma16816(acc1[2 * gp + 1], al, b[2], b[3]);
                    }
                }
            }
            if (u == 3) {
                // H = relu(acc1 + b1) -> split -> SMEM
                const float* sB1 = reinterpret_cast<const float*>(smem + SM_B1) + hc * 128;
#pragma unroll
                for (int g = 0; g < 8; g++) {
                    int col = (wn << 6) + g * 8 + ((lane & 3) << 1);
                    float b0 = sB1[col], b1v = sB1[col + 1];
                    float h0 = fmaxf(acc1[g][0] + b0, 0.0f);
                    float h1 = fmaxf(acc1[g][1] + b1v, 0.0f);
                    float h2 = fmaxf(acc1[g][2] + b0, 0.0f);
                    float h3 = fmaxf(acc1[g][3] + b1v, 0.0f);
                    __nv_bfloat16 h0h = __float2bfloat16_rn(h0), h1h = __float2bfloat16_rn(h1);
                    __nv_bfloat16 h2h = __float2bfloat16_rn(h2), h3h = __float2bfloat16_rn(h3);
                    __nv_bfloat16 h0l = __float2bfloat16_rn(h0 - __bfloat162float(h0h));
                    __nv_bfloat16 h1l = __float2bfloat16_rn(h1 - __bfloat162float(h1h));
                    __nv_bfloat16 h2l = __float2bfloat16_rn(h2 - __bfloat162float(h2h));
                    __nv_bfloat16 h3l = __float2bfloat16_rn(h3 - __bfloat162float(h3h));
                    uint32_t chunk = (uint32_t)(col >> 3);
                    uint32_t swc = ((chunk & 8) | ((chunk ^ (uint32_t)rE7) & 7)) << 4;
                    uint32_t byt = ((uint32_t)rE << 8) + swc + (uint32_t)((col & 7) << 1);
                    *reinterpret_cast<uint32_t*>(smem + SM_HH + byt) = pack_bf(h0h, h1h);
                    *reinterpret_cast<uint32_t*>(smem + SM_HL + byt) = pack_bf(h0l, h1l);
                    uint32_t byt2 = byt + (8u << 8);
                    *reinterpret_cast<uint32_t*>(smem + SM_HH + byt2) = pack_bf(h2h, h3h);
                    *reinterpret_cast<uint32_t*>(smem + SM_HL + byt2) = pack_bf(h2l, h3l);
                }
            }
        } else {
            int ks2 = u & 1;
            int np = (u < 6) ? 2 : 1;   // hi-W: H hi+lo ; lo-W: H hi
            uint32_t bslab = wbase + ((uint32_t)wn << 14);
#pragma unroll
            for (int s = 0; s < 4; s++) {
                uint32_t ch = (uint32_t)(ks2 * 8 + s * 2 + ka);
                uint32_t swh = ((ch & 8) | ((ch ^ (uint32_t)ar7) & 7)) << 4;
                uint32_t ah[4], al[4];
                ldm4(ah, sb + SM_HH + hRowOff + swh);
                if (np == 2) ldm4(al, sb + SM_HL + hRowOff + swh);
                uint32_t swb = (uint32_t)((((s * 2 + bk) ^ l7) & 7) << 4);
#pragma unroll
                for (int gp = 0; gp < 8; gp++) {
                    uint32_t b[4];
                    ldm4(b, bslab + ((uint32_t)(gp * 16 + rowB7) << 7) + swb);
                    mma16816(acc2[2 * gp],     ah, b[0], b[1]);
                    mma16816(acc2[2 * gp + 1], ah, b[2], b[3]);
                    if (np == 2) {
                        mma16816(acc2[2 * gp],     al, b[0], b[1]);
                        mma16816(acc2[2 * gp + 1], al, b[2], b[3]);
                    }
                }
            }
        }
    }

    // ---- final epilogue ----
    const float* sB2 = reinterpret_cast<const float*>(smem + SM_B2);
    int idx0 = m0 + rE, idx1 = idx0 + 8;
    if (sh) {
        float* p0 = out + (size_t)idx0 * DIM;
        float* p1 = out + (size_t)idx1 * DIM;
#pragma unroll
        for (int g = 0; g < 16; g++) {
            int col = (wn << 7) + g * 8 + ((lane & 3) << 1);
            float b0 = sB2[col], b1v = sB2[col + 1];
            float2 v0, v1;
            v0.x = acc2[g][0] + b0; v0.y = acc2[g][1] + b1v;
            v1.x = acc2[g][2] + b0; v1.y = acc2[g][3] + b1v;
            *reinterpret_cast<float2*>(p0 + col) = v0;
            *reinterpret_cast<float2*>(p1 + col) = v1;
        }
    } else {
        bool act0 = idx0 < cnt, act1 = idx1 < cnt;
        float cw0 = act0 ? g_wt[e][idx0] : 0.0f;
        float cw1 = act1 ? g_wt[e][idx1] : 0.0f;
        int t0 = act0 ? g_tok[e][idx0] : 0;
        int t1 = act1 ? g_tok[e][idx1] : 0;
        float* p0 = out + (size_t)t0 * DIM;
        float* p1 = out + (size_t)t1 * DIM;
#pragma unroll
        for (int g = 0; g < 16; g++) {
            int col = (wn << 7) + g * 8 + ((lane & 3) << 1);
            float b0 = sB2[col], b1v = sB2[col + 1];
            if (act0) {
                atomicAdd(p0 + col,     cw0 * (acc2[g][0] + b0));
                atomicAdd(p0 + col + 1, cw0 * (acc2[g][1] + b1v));
            }
            if (act1) {
                atomicAdd(p1 + col,     cw1 * (acc2[g][2] + b0));
                atomicAdd(p1 + col + 1, cw1 * (acc2[g][3] + b1v));
            }
        }
    }
}

__global__ void k_aux(float* out_aux) {
    if (threadIdx.x == 0) {
        float a = 0.0f;
        for (int e = 0; e < NE; e++) {
            float imp  = g_imp[e] / (float)T_TOKENS;
            float load = (float)g_cnt[e] / (float)(2 * T_TOKENS);
            a += imp * load;
        }
        out_aux[0] = (float)NE * a;
    }
}

// ---------------------------------------------------------------------------
extern "C" void kernel_launch(void* const* d_in, const int* in_sizes, int n_in,
                              void* d_out, int out_size) {
    const float* x   = (const float*)d_in[0];
    const float* rw  = (const float*)d_in[1];
    const float* rb  = (const float*)d_in[2];
    const float* w1  = (const float*)d_in[3];
    const float* b1  = (const float*)d_in[4];
    const float* w2  = (const float*)d_in[5];
    const float* b2  = (const float*)d_in[6];
    const float* sw1 = (const float*)d_in[7];
    const float* sb1 = (const float*)d_in[8];
    const float* sw2 = (const float*)d_in[9];
    const float* sb2 = (const float*)d_in[10];
    float* out = (float*)d_out;
    (void)in_sizes; (void)n_in;

    cudaFuncSetAttribute(k_moe, cudaFuncAttributeMaxDynamicSharedMemorySize, SMEM_TOTAL);

    k_zero<<<1, 32>>>();
    k_router<<<T_TOKENS / 256, 256>>>(x, rw, rb);
    k_prepw1<<<(NEXP * HID * DIM) / 256, 256>>>(w1, sw1);
    k_prepw2<<<(NEXP * DIM * HID) / 256, 256>>>(w2, sw2);
    k_prepb<<<(NEXP * (HID + DIM) + 255) / 256, 256>>>(b1, sb1, b2, sb2);

    // shared expert: direct writes (initializes out)
    k_moe<<<T_TOKENS / 64, 256, SMEM_TOTAL>>>(0, x, out);
    // routed experts: atomic accumulate
    dim3 gr(T_TOKENS / 64, NE);
    k_moe<<<gr, 256, SMEM_TOTAL>>>(1, x, out);

    if (out_size > T_TOKENS * DIM) {
        k_aux<<<1, 32>>>(out + (size_t)T_TOKENS * DIM);
    }
}